// round 10
// baseline (speedup 1.0000x reference)
#include <cuda_runtime.h>
#include <cuda_bf16.h>
#include <math.h>
#include <stdint.h>

#define DIM   4096
#define S_LEN 2048
#define HD    128
#define NH    32
#define NKV   8
#define KVDIM (NKV*HD)   // 1024
#define KTOT  4096
#define NQKV  (DIM + 2*KVDIM)   // 6144

// ======================= scratch globals ===================================
__device__ __nv_bfloat16 g_xhi [S_LEN * DIM];
__device__ __nv_bfloat16 g_xlo [S_LEN * DIM];
__device__ __nv_bfloat16 g_wqkvt_hi[NQKV * KTOT];   // rows: wq^T | wk^T | wv^T
__device__ __nv_bfloat16 g_wqkvt_lo[NQKV * KTOT];
__device__ __nv_bfloat16 g_wot_hi[DIM * DIM];
__device__ __nv_bfloat16 g_wot_lo[DIM * DIM];
__device__ __nv_bfloat16 g_qhi [S_LEN * DIM];
__device__ __nv_bfloat16 g_qlo [S_LEN * DIM];
__device__ __nv_bfloat16 g_khi [S_LEN * KVDIM];
__device__ __nv_bfloat16 g_klo [S_LEN * KVDIM];
__device__ __nv_bfloat16 g_vhi [S_LEN * KVDIM];
__device__ __nv_bfloat16 g_vlo [S_LEN * KVDIM];
__device__ __nv_bfloat16 g_atthi[S_LEN * DIM];
__device__ __nv_bfloat16 g_attlo[S_LEN * DIM];

// ======================= asm helpers (sm_100-safe) =========================
__device__ __forceinline__ uint32_t smem_u32(const void* p) {
    uint32_t a;
    asm("{ .reg .u64 t; cvta.to.shared.u64 t, %1; cvt.u32.u64 %0, t; }"
        : "=r"(a) : "l"(p));
    return a;
}
#define CP_ASYNC16(dst, src) \
    asm volatile("cp.async.cg.shared.global [%0], [%1], 16;" :: "r"(dst), "l"(src))
#define CP_COMMIT()  asm volatile("cp.async.commit_group;" ::: "memory")
#define CP_WAIT0()   asm volatile("cp.async.wait_group 0;"  ::: "memory")
#define CP_WAIT2()   asm volatile("cp.async.wait_group 2;"  ::: "memory")

__device__ __forceinline__ void ldsm_x4(uint32_t* r, uint32_t addr) {
    asm volatile("ldmatrix.sync.aligned.m8n8.x4.shared.b16 {%0,%1,%2,%3}, [%4];"
                 : "=r"(r[0]), "=r"(r[1]), "=r"(r[2]), "=r"(r[3]) : "r"(addr));
}
__device__ __forceinline__ void ldsm_x4t(uint32_t* r, uint32_t addr) {
    asm volatile("ldmatrix.sync.aligned.m8n8.x4.trans.shared.b16 {%0,%1,%2,%3}, [%4];"
                 : "=r"(r[0]), "=r"(r[1]), "=r"(r[2]), "=r"(r[3]) : "r"(addr));
}
__device__ __forceinline__ void mma16816(float* c, const uint32_t* a, const uint32_t* b) {
    asm volatile("mma.sync.aligned.m16n8k16.row.col.f32.bf16.bf16.f32 "
                 "{%0,%1,%2,%3}, {%4,%5,%6,%7}, {%8,%9}, {%0,%1,%2,%3};"
                 : "+f"(c[0]), "+f"(c[1]), "+f"(c[2]), "+f"(c[3])
                 : "r"(a[0]), "r"(a[1]), "r"(a[2]), "r"(a[3]), "r"(b[0]), "r"(b[1]));
}
__device__ __forceinline__ uint32_t pack_bf16(float a, float b) {
    __nv_bfloat162 h = __floats2bfloat162_rn(a, b);
    return *(uint32_t*)&h;
}

// ======================= conversion kernels ================================
__global__ __launch_bounds__(256)
void split_kernel(const float* __restrict__ in, __nv_bfloat16* __restrict__ hi,
                  __nv_bfloat16* __restrict__ lo, int n4)
{
    int i = blockIdx.x * blockDim.x + threadIdx.x;
    if (i >= n4) return;
    float4 v = ((const float4*)in)[i];
    __nv_bfloat16 h0 = __float2bfloat16(v.x), h1 = __float2bfloat16(v.y);
    __nv_bfloat16 h2 = __float2bfloat16(v.z), h3 = __float2bfloat16(v.w);
    __nv_bfloat16 l0 = __float2bfloat16(v.x - __bfloat162float(h0));
    __nv_bfloat16 l1 = __float2bfloat16(v.y - __bfloat162float(h1));
    __nv_bfloat16 l2 = __float2bfloat16(v.z - __bfloat162float(h2));
    __nv_bfloat16 l3 = __float2bfloat16(v.w - __bfloat162float(h3));
    ushort4 hv = make_ushort4(*(unsigned short*)&h0, *(unsigned short*)&h1,
                              *(unsigned short*)&h2, *(unsigned short*)&h3);
    ushort4 lv = make_ushort4(*(unsigned short*)&l0, *(unsigned short*)&l1,
                              *(unsigned short*)&l2, *(unsigned short*)&l3);
    ((ushort4*)hi)[i] = hv;
    ((ushort4*)lo)[i] = lv;
}

// W[K][N] fp32 -> Thi/Tlo[N][K] bf16 (transpose + split); caller offsets T base.
__global__ __launch_bounds__(256)
void transpose_split_kernel(const float* __restrict__ W, __nv_bfloat16* __restrict__ Thi,
                            __nv_bfloat16* __restrict__ Tlo, int K, int N)
{
    __shared__ float t[32][33];
    int n0 = blockIdx.x * 32, k0 = blockIdx.y * 32;
    int tx = threadIdx.x & 31, ty = threadIdx.x >> 5;
#pragma unroll
    for (int i = 0; i < 4; i++)
        t[ty + i * 8][tx] = W[(size_t)(k0 + ty + i * 8) * N + n0 + tx];
    __syncthreads();
#pragma unroll
    for (int i = 0; i < 4; i++) {
        float a = t[tx][ty + i * 8];
        __nv_bfloat16 h = __float2bfloat16(a);
        __nv_bfloat16 l = __float2bfloat16(a - __bfloat162float(h));
        size_t o = (size_t)(n0 + ty + i * 8) * K + k0 + tx;
        Thi[o] = h; Tlo[o] = l;
    }
}

// ======================= mma.sync GEMM =====================================
// BM=BN=128, BK=16, 4-stage cp.async pipeline (wait_group 2), 256 thr,
// warps 4x2, warp tile 32x64, x4 B-frag loads. 3-product split-bf16.
// MODE 0: fp32 C out (O projection).  MODE 1: fused QKV, per-CTA dispatch.
#define GSTAGES   4
#define GSTRIDE   24                        // elements per smem row (48 B)
#define GS_MAT    (128 * GSTRIDE * 2)       // 6144 B per split-matrix
#define GS_STAGE  (4 * GS_MAT)              // 24576 B: Ahi|Alo|Bhi|Blo
#define GEMM_SMEM_BYTES (GSTAGES * GS_STAGE)  // 98304
#define NK16      (KTOT / 16)               // 256 iterations

template<int MODE>
__global__ __launch_bounds__(256, 2)
void gemm_mma(const __nv_bfloat16* __restrict__ Ahi, const __nv_bfloat16* __restrict__ Alo,
              const __nv_bfloat16* __restrict__ Bhi, const __nv_bfloat16* __restrict__ Blo,
              float* __restrict__ C,
              const float* __restrict__ fcos, const float* __restrict__ fsin)
{
    extern __shared__ char smem[];
    const uint32_t sbase = smem_u32(smem);
    const int tid  = threadIdx.x;
    const int lane = tid & 31;
    const int wid  = tid >> 5;
    const int wm   = wid & 3;
    const int wn   = wid >> 2;
    const int rowBase = blockIdx.y * 128;
    const int colBase = blockIdx.x * 128;

    // per-thread load slot: row = tid>>1 (0..127), chunk = (tid&1)*8 elements
    const int ldRow = tid >> 1;
    const int ldCh  = (tid & 1) * 8;
    const uint32_t ldSm = (uint32_t)(ldRow * GSTRIDE + ldCh) * 2;

    auto prefetch = [&](int slot, int k0) {
        uint32_t st = sbase + (uint32_t)slot * GS_STAGE;
        size_t ga = (size_t)(rowBase + ldRow) * KTOT + k0 + ldCh;
        size_t gb = (size_t)(colBase + ldRow) * KTOT + k0 + ldCh;
        CP_ASYNC16(st + 0 * GS_MAT + ldSm, Ahi + ga);
        CP_ASYNC16(st + 1 * GS_MAT + ldSm, Alo + ga);
        CP_ASYNC16(st + 2 * GS_MAT + ldSm, Bhi + gb);
        CP_ASYNC16(st + 3 * GS_MAT + ldSm, Blo + gb);
        CP_COMMIT();
    };

    float acc[2][8][4];
#pragma unroll
    for (int mi = 0; mi < 2; mi++)
#pragma unroll
        for (int ni = 0; ni < 8; ni++)
#pragma unroll
            for (int r = 0; r < 4; r++) acc[mi][ni][r] = 0.0f;

    const int am  = (lane & 7) + ((lane >> 3) & 1) * 8;
    const int ak  = (lane >> 4) * 8;
    const int bn4 = (lane & 7) + ((lane >> 4) & 1) * 8;
    const int bk4 = ((lane >> 3) & 1) * 8;

    prefetch(0, 0);
    prefetch(1, 16);
    prefetch(2, 32);

    for (int i = 0; i < NK16; i++) {
        CP_WAIT2();
        __syncthreads();
        if (i + 3 < NK16) prefetch((i + 3) & 3, (i + 3) * 16);
        else              CP_COMMIT();      // keep outstanding-group invariant

        const uint32_t st  = sbase + (uint32_t)(i & 3) * GS_STAGE;
        const uint32_t aHiB = st, aLoB = st + GS_MAT;
        const uint32_t bHiB = st + 2 * GS_MAT, bLoB = st + 3 * GS_MAT;

        uint32_t aHi[2][4], aLo[2][4];
#pragma unroll
        for (int mi = 0; mi < 2; mi++) {
            uint32_t off = (uint32_t)((wm * 32 + mi * 16 + am) * GSTRIDE + ak) * 2;
            ldsm_x4(aHi[mi], aHiB + off);
            ldsm_x4(aLo[mi], aLoB + off);
        }
#pragma unroll
        for (int ni2 = 0; ni2 < 4; ni2++) {
            uint32_t boff = (uint32_t)((wn * 64 + ni2 * 16 + bn4) * GSTRIDE + bk4) * 2;
            uint32_t bh[4];
            ldsm_x4(bh, bHiB + boff);
#pragma unroll
            for (int mi = 0; mi < 2; mi++) {
                mma16816(acc[mi][2 * ni2],     aHi[mi], bh);
                mma16816(acc[mi][2 * ni2 + 1], aHi[mi], bh + 2);
                mma16816(acc[mi][2 * ni2],     aLo[mi], bh);
                mma16816(acc[mi][2 * ni2 + 1], aLo[mi], bh + 2);
            }
            uint32_t bl[4];
            ldsm_x4(bl, bLoB + boff);
#pragma unroll
            for (int mi = 0; mi < 2; mi++) {
                mma16816(acc[mi][2 * ni2],     aHi[mi], bl);
                mma16816(acc[mi][2 * ni2 + 1], aHi[mi], bl + 2);
            }
        }
        // no bottom barrier: prefetch at iter i+1 targets stage (i-1)&3,
        // whose readers all passed the iter-(i+1) top barrier.
    }

    // ---- epilogue ----
    const int qrow = lane >> 2;
    const int qcol = (lane & 3) * 2;

    __nv_bfloat16 *Chi = nullptr, *Clo = nullptr;
    int Nout = DIM, colOff = colBase;
    bool rope = false;
    float osc = 1.0f;
    if (MODE == 1) {
        if (colBase < DIM) {
            Chi = g_qhi; Clo = g_qlo; Nout = DIM; colOff = colBase;
            rope = true; osc = 0.08838834764831844f;     // 1/sqrt(128)
        } else if (colBase < DIM + KVDIM) {
            Chi = g_khi; Clo = g_klo; Nout = KVDIM; colOff = colBase - DIM;
            rope = true;
        } else {
            Chi = g_vhi; Clo = g_vlo; Nout = KVDIM; colOff = colBase - DIM - KVDIM;
        }
    }

#pragma unroll
    for (int mi = 0; mi < 2; mi++) {
#pragma unroll
        for (int half = 0; half < 2; half++) {
            int r = rowBase + wm * 32 + mi * 16 + qrow + half * 8;
#pragma unroll
            for (int ni = 0; ni < 8; ni++) {
                int n_g = colOff + wn * 64 + ni * 8 + qcol;
                float c0 = acc[mi][ni][half * 2];
                float c1 = acc[mi][ni][half * 2 + 1];
                float ox, oy;
                if (MODE == 1 && rope) {
                    int d = (n_g & (HD - 1)) >> 1;
                    float fc = fcos[r * (HD / 2) + d];
                    float fs = fsin[r * (HD / 2) + d];
                    ox = c0 * fc - c1 * fs;
                    oy = c0 * fs + c1 * fc;
                } else {
                    ox = c0; oy = c1;
                }
                if (MODE == 1) {
                    ox *= osc; oy *= osc;
                    __nv_bfloat16 h0 = __float2bfloat16(ox);
                    __nv_bfloat16 h1 = __float2bfloat16(oy);
                    float l0f = ox - __bfloat162float(h0);
                    float l1f = oy - __bfloat162float(h1);
                    size_t o = (size_t)r * Nout + n_g;
                    *(uint32_t*)&Chi[o] = pack_bf16(__bfloat162float(h0), __bfloat162float(h1));
                    *(uint32_t*)&Clo[o] = pack_bf16(l0f, l1f);
                } else {
                    *(float2*)&C[(size_t)r * DIM + n_g] = make_float2(ox, oy);
                }
            }
        }
    }
}

// ======================= flash attention (mma.sync) ========================
#define FPAD 136
#define FQ_BYTES   (128 * FPAD * 2)
#define FT_BYTES   (64 * FPAD * 2)
#define FKV_BYTES  (4 * FT_BYTES)
#define FLASH_SMEM (2 * FQ_BYTES + 2 * FKV_BYTES)   // 208896

__global__ __launch_bounds__(256, 1)
void flash_mma(const __nv_bfloat16* __restrict__ qhi, const __nv_bfloat16* __restrict__ qlo,
               const __nv_bfloat16* __restrict__ khi, const __nv_bfloat16* __restrict__ klo,
               const __nv_bfloat16* __restrict__ vhi, const __nv_bfloat16* __restrict__ vlo,
               __nv_bfloat16* __restrict__ atthi, __nv_bfloat16* __restrict__ attlo)
{
    extern __shared__ char smem[];
    const uint32_t sbase = smem_u32(smem);
    const int tid  = threadIdx.x;
    const int lane = tid & 31;
    const int w    = tid >> 5;
    const int qt   = gridDim.x - 1 - blockIdx.x;
    const int head = blockIdx.y;
    const int kvh  = head >> 2;
    const int qbase = qt * 128;
    const int ktmax = 2 * qt + 1;

    const uint32_t QHI = sbase;
    const uint32_t QLO = sbase + FQ_BYTES;
    const uint32_t KVB = sbase + 2 * FQ_BYTES;

#pragma unroll
    for (int t = 0; t < 16; t++) {
        int c = tid + t * 256;
        int arr = c >> 11;
        int rem = c & 2047;
        int row = rem >> 4;
        int ch  = rem & 15;
        const __nv_bfloat16* src = arr ? qlo : qhi;
        uint32_t dst = (arr ? QLO : QHI) + (uint32_t)(row * FPAD + ch * 8) * 2;
        CP_ASYNC16(dst, src + (size_t)(qbase + row) * DIM + head * HD + ch * 8);
    }
    auto load_kv = [&](int buf, int kt) {
        const int kbase = kt * 64;
        uint32_t base = KVB + (uint32_t)buf * FKV_BYTES;
#pragma unroll
        for (int t = 0; t < 16; t++) {
            int c = tid + t * 256;
            int arr = c >> 10;
            int rem = c & 1023;
            int row = rem >> 4;
            int ch  = rem & 15;
            const __nv_bfloat16* src = (arr == 0) ? khi : (arr == 1) ? klo
                                     : (arr == 2) ? vhi : vlo;
            uint32_t dst = base + (uint32_t)arr * FT_BYTES + (uint32_t)(row * FPAD + ch * 8) * 2;
            CP_ASYNC16(dst, src + (size_t)(kbase + row) * KVDIM + kvh * HD + ch * 8);
        }
        CP_COMMIT();
    };
    load_kv(0, 0);   // one commit covering Q + tile 0

    const int am  = (lane & 7) + ((lane >> 3) & 1) * 8;
    const int ak  = (lane >> 4) * 8;
    const int kn4 = (lane & 7) + ((lane >> 4) & 1) * 8;   // K x4: row in n16
    const int kk4 = ((lane >> 3) & 1) * 8;                // K x4: k offset
    const int vrow = ((lane >> 3) & 1) * 8 + (lane & 7);  // V x4t: k row
    const int vcol = ((lane >> 4) & 1) * 8;               // V x4t: d col select
    const int qrow = lane >> 2;
    const int qcol = (lane & 3) * 2;

    float O[16][4];
#pragma unroll
    for (int ni = 0; ni < 16; ni++)
#pragma unroll
        for (int r = 0; r < 4; r++) O[ni][r] = 0.0f;
    float m0 = -1e30f, m1 = -1e30f, l0 = 0.0f, l1 = 0.0f;

    for (int kt = 0; kt <= ktmax; kt++) {
        CP_WAIT0();
        __syncthreads();
        if (kt + 1 <= ktmax) load_kv((kt + 1) & 1, kt + 1);

        const uint32_t base = KVB + (uint32_t)(kt & 1) * FKV_BYTES;
        const uint32_t KHI = base, KLO = base + FT_BYTES;
        const uint32_t VHI = base + 2 * FT_BYTES, VLO = base + 3 * FT_BYTES;

        float S[8][4];
#pragma unroll
        for (int j = 0; j < 8; j++)
#pragma unroll
            for (int r = 0; r < 4; r++) S[j][r] = 0.0f;

#pragma unroll
        for (int ks = 0; ks < 8; ks++) {
            uint32_t qh[4], ql[4];
            uint32_t qoff = (uint32_t)((w * 16 + am) * FPAD + ks * 16 + ak) * 2;
            ldsm_x4(qh, QHI + qoff);
            ldsm_x4(ql, QLO + qoff);
#pragma unroll
            for (int jp = 0; jp < 4; jp++) {
                uint32_t koff = (uint32_t)((jp * 16 + kn4) * FPAD + ks * 16 + kk4) * 2;
                uint32_t kh[4], kl[4];
                ldsm_x4(kh, KHI + koff);
                ldsm_x4(kl, KLO + koff);
                mma16816(S[2 * jp],     qh, kh);
                mma16816(S[2 * jp + 1], qh, kh + 2);
                mma16816(S[2 * jp],     ql, kh);
                mma16816(S[2 * jp + 1], ql, kh + 2);
                mma16816(S[2 * jp],     qh, kl);
                mma16816(S[2 * jp + 1], qh, kl + 2);
            }
        }

        if (kt >= 2 * qt) {
            const int kbase = kt * 64;
            int gq0 = qbase + w * 16 + qrow;
            int gq1 = gq0 + 8;
#pragma unroll
            for (int j = 0; j < 8; j++) {
                int gk = kbase + j * 8 + qcol;
                if (gk     > gq0) S[j][0] = -1e30f;
                if (gk + 1 > gq0) S[j][1] = -1e30f;
                if (gk     > gq1) S[j][2] = -1e30f;
                if (gk + 1 > gq1) S[j][3] = -1e30f;
            }
        }

        float mx0 = -1e30f, mx1 = -1e30f;
#pragma unroll
        for (int j = 0; j < 8; j++) {
            mx0 = fmaxf(mx0, fmaxf(S[j][0], S[j][1]));
            mx1 = fmaxf(mx1, fmaxf(S[j][2], S[j][3]));
        }
        mx0 = fmaxf(mx0, __shfl_xor_sync(0xffffffffu, mx0, 1));
        mx0 = fmaxf(mx0, __shfl_xor_sync(0xffffffffu, mx0, 2));
        mx1 = fmaxf(mx1, __shfl_xor_sync(0xffffffffu, mx1, 1));
        mx1 = fmaxf(mx1, __shfl_xor_sync(0xffffffffu, mx1, 2));

        float m0n = fmaxf(m0, mx0), m1n = fmaxf(m1, mx1);
        float a0 = __expf(m0 - m0n), a1 = __expf(m1 - m1n);
        float s0 = 0.0f, s1 = 0.0f;
#pragma unroll
        for (int j = 0; j < 8; j++) {
            S[j][0] = __expf(S[j][0] - m0n);
            S[j][1] = __expf(S[j][1] - m0n);
            S[j][2] = __expf(S[j][2] - m1n);
            S[j][3] = __expf(S[j][3] - m1n);
            s0 += S[j][0] + S[j][1];
            s1 += S[j][2] + S[j][3];
        }
        s0 += __shfl_xor_sync(0xffffffffu, s0, 1);
        s0 += __shfl_xor_sync(0xffffffffu, s0, 2);
        s1 += __shfl_xor_sync(0xffffffffu, s1, 1);
        s1 += __shfl_xor_sync(0xffffffffu, s1, 2);
        l0 = l0 * a0 + s0;  m0 = m0n;
        l1 = l1 * a1 + s1;  m1 = m1n;
#pragma unroll
        for (int ni = 0; ni < 16; ni++) {
            O[ni][0] *= a0; O[ni][1] *= a0;
            O[ni][2] *= a1; O[ni][3] *= a1;
        }

#pragma unroll
        for (int kt2 = 0; kt2 < 4; kt2++) {
            uint32_t ph[4], pl[4];
#pragma unroll
            for (int half = 0; half < 2; half++) {
                float p0 = S[2 * kt2 + half][0], p1 = S[2 * kt2 + half][1];
                float p2 = S[2 * kt2 + half][2], p3 = S[2 * kt2 + half][3];
                float h0 = __bfloat162float(__float2bfloat16(p0));
                float h1 = __bfloat162float(__float2bfloat16(p1));
                float h2 = __bfloat162float(__float2bfloat16(p2));
                float h3 = __bfloat162float(__float2bfloat16(p3));
                ph[half * 2 + 0] = pack_bf16(h0, h1);
                ph[half * 2 + 1] = pack_bf16(h2, h3);
                pl[half * 2 + 0] = pack_bf16(p0 - h0, p1 - h1);
                pl[half * 2 + 1] = pack_bf16(p2 - h2, p3 - h3);
            }
#pragma unroll
            for (int nip = 0; nip < 8; nip++) {
                uint32_t voff = (uint32_t)((kt2 * 16 + vrow) * FPAD + nip * 16 + vcol) * 2;
                uint32_t vh[4], vl[4];
                ldsm_x4t(vh, VHI + voff);
                ldsm_x4t(vl, VLO + voff);
                mma16816(O[2 * nip],     ph, vh);
                mma16816(O[2 * nip + 1], ph, vh + 2);
                mma16816(O[2 * nip],     pl, vh);
                mma16816(O[2 * nip + 1], pl, vh + 2);
                mma16816(O[2 * nip],     ph, vl);
                mma16816(O[2 * nip + 1], ph, vl + 2);
            }
        }
    }

    float inv0 = 1.0f / l0, inv1 = 1.0f / l1;
    int gq0 = qbase + w * 16 + qrow;
    int gq1 = gq0 + 8;
#pragma unroll
    for (int ni = 0; ni < 16; ni++) {
        int col = head * HD + ni * 8 + qcol;
        float o0 = O[ni][0] * inv0, o1 = O[ni][1] * inv0;
        float o2 = O[ni][2] * inv1, o3 = O[ni][3] * inv1;
        float h0 = __bfloat162float(__float2bfloat16(o0));
        float h1 = __bfloat162float(__float2bfloat16(o1));
        float h2 = __bfloat162float(__float2bfloat16(o2));
        float h3 = __bfloat162float(__float2bfloat16(o3));
        size_t p0 = (size_t)gq0 * DIM + col;
        size_t p1 = (size_t)gq1 * DIM + col;
        *(uint32_t*)&atthi[p0] = pack_bf16(h0, h1);
        *(uint32_t*)&attlo[p0] = pack_bf16(o0 - h0, o1 - h1);
        *(uint32_t*)&atthi[p1] = pack_bf16(h2, h3);
        *(uint32_t*)&attlo[p1] = pack_bf16(o2 - h2, o3 - h3);
    }
}

// ======================= launch ============================================
extern "C" void kernel_launch(void* const* d_in, const int* in_sizes, int n_in,
                              void* d_out, int out_size)
{
    const float* x    = (const float*)d_in[0];
    const float* wq   = (const float*)d_in[1];
    const float* wk   = (const float*)d_in[2];
    const float* wv   = (const float*)d_in[3];
    const float* wo   = (const float*)d_in[4];
    const float* fcos = (const float*)d_in[5];
    const float* fsin = (const float*)d_in[6];
    float* out = (float*)d_out;

    __nv_bfloat16 *xhi, *xlo, *wqkvth, *wqkvtl, *woth, *wotl;
    __nv_bfloat16 *qhi, *qlo, *khi, *klo, *vhi, *vlo, *atthi, *attlo;
    cudaGetSymbolAddress((void**)&xhi,   g_xhi);
    cudaGetSymbolAddress((void**)&xlo,   g_xlo);
    cudaGetSymbolAddress((void**)&wqkvth,g_wqkvt_hi);
    cudaGetSymbolAddress((void**)&wqkvtl,g_wqkvt_lo);
    cudaGetSymbolAddress((void**)&woth,  g_wot_hi);
    cudaGetSymbolAddress((void**)&wotl,  g_wot_lo);
    cudaGetSymbolAddress((void**)&qhi,   g_qhi);
    cudaGetSymbolAddress((void**)&qlo,   g_qlo);
    cudaGetSymbolAddress((void**)&khi,   g_khi);
    cudaGetSymbolAddress((void**)&klo,   g_klo);
    cudaGetSymbolAddress((void**)&vhi,   g_vhi);
    cudaGetSymbolAddress((void**)&vlo,   g_vlo);
    cudaGetSymbolAddress((void**)&atthi, g_atthi);
    cudaGetSymbolAddress((void**)&attlo, g_attlo);

    cudaFuncSetAttribute(gemm_mma<0>,
                         cudaFuncAttributeMaxDynamicSharedMemorySize, GEMM_SMEM_BYTES);
    cudaFuncSetAttribute(gemm_mma<1>,
                         cudaFuncAttributeMaxDynamicSharedMemorySize, GEMM_SMEM_BYTES);
    cudaFuncSetAttribute(flash_mma,
                         cudaFuncAttributeMaxDynamicSharedMemorySize, FLASH_SMEM);

    int n4x = S_LEN * DIM / 4;

    split_kernel<<<(n4x + 255) / 256, 256>>>(x, xhi, xlo, n4x);
    transpose_split_kernel<<<dim3(DIM / 32,   DIM / 32), 256>>>(
        wq, wqkvth, wqkvtl, KTOT, DIM);
    transpose_split_kernel<<<dim3(KVDIM / 32, DIM / 32), 256>>>(
        wk, wqkvth + (size_t)DIM * KTOT, wqkvtl + (size_t)DIM * KTOT, KTOT, KVDIM);
    transpose_split_kernel<<<dim3(KVDIM / 32, DIM / 32), 256>>>(
        wv, wqkvth + (size_t)(DIM + KVDIM) * KTOT, wqkvtl + (size_t)(DIM + KVDIM) * KTOT,
        KTOT, KVDIM);
    transpose_split_kernel<<<dim3(DIM / 32,   DIM / 32), 256>>>(wo, woth, wotl, KTOT, DIM);

    gemm_mma<1><<<dim3(NQKV / 128, S_LEN / 128), 256, GEMM_SMEM_BYTES>>>(
        xhi, xlo, wqkvth, wqkvtl, nullptr, fcos, fsin);

    flash_mma<<<dim3(S_LEN / 128, NH), 256, FLASH_SMEM>>>(
        qhi, qlo, khi, klo, vhi, vlo, atthi, attlo);

    gemm_mma<0><<<dim3(DIM / 128, S_LEN / 128), 256, GEMM_SMEM_BYTES>>>(
        atthi, attlo, woth, wotl, out, nullptr, nullptr);
}

// round 13
// speedup vs baseline: 1.6384x; 1.6384x over previous
#include <cuda_runtime.h>
#include <cuda_fp16.h>
#include <math.h>
#include <stdint.h>

#define DIM   4096
#define S_LEN 2048
#define HD    128
#define NH    32
#define NKV   8
#define KVDIM (NKV*HD)   // 1024
#define KTOT  4096
#define NK    (KTOT/32)  // 128
#define NQKV  (DIM + 2*KVDIM)   // 6144

// ======================= scratch globals ===================================
__device__ __half g_xhi [S_LEN * DIM];
__device__ __half g_xlo [S_LEN * DIM];
__device__ __half g_wqkvt[NQKV * KTOT];   // single fp16: wq^T | wk^T | wv^T
__device__ __half g_wot  [DIM * KTOT];
__device__ __half g_qhi [S_LEN * DIM];
__device__ __half g_qlo [S_LEN * DIM];
__device__ __half g_k   [S_LEN * KVDIM];
__device__ __half g_v   [S_LEN * KVDIM];
__device__ __half g_atthi[S_LEN * DIM];
__device__ __half g_attlo[S_LEN * DIM];

// ======================= asm helpers (sm_100-safe) =========================
__device__ __forceinline__ uint32_t smem_u32(const void* p) {
    uint32_t a;
    asm("{ .reg .u64 t; cvta.to.shared.u64 t, %1; cvt.u32.u64 %0, t; }"
        : "=r"(a) : "l"(p));
    return a;
}
#define CP_ASYNC16(dst, src) \
    asm volatile("cp.async.cg.shared.global [%0], [%1], 16;" :: "r"(dst), "l"(src))
#define CP_COMMIT()  asm volatile("cp.async.commit_group;" ::: "memory")
#define CP_WAIT0()   asm volatile("cp.async.wait_group 0;"  ::: "memory")
#define CP_WAIT1()   asm volatile("cp.async.wait_group 1;"  ::: "memory")

__device__ __forceinline__ void ldsm_x4(uint32_t* r, uint32_t addr) {
    asm volatile("ldmatrix.sync.aligned.m8n8.x4.shared.b16 {%0,%1,%2,%3}, [%4];"
                 : "=r"(r[0]), "=r"(r[1]), "=r"(r[2]), "=r"(r[3]) : "r"(addr));
}
__device__ __forceinline__ void ldsm_x4t(uint32_t* r, uint32_t addr) {
    asm volatile("ldmatrix.sync.aligned.m8n8.x4.trans.shared.b16 {%0,%1,%2,%3}, [%4];"
                 : "=r"(r[0]), "=r"(r[1]), "=r"(r[2]), "=r"(r[3]) : "r"(addr));
}
__device__ __forceinline__ void mma16816h(float* c, const uint32_t* a, const uint32_t* b) {
    asm volatile("mma.sync.aligned.m16n8k16.row.col.f32.f16.f16.f32 "
                 "{%0,%1,%2,%3}, {%4,%5,%6,%7}, {%8,%9}, {%0,%1,%2,%3};"
                 : "+f"(c[0]), "+f"(c[1]), "+f"(c[2]), "+f"(c[3])
                 : "r"(a[0]), "r"(a[1]), "r"(a[2]), "r"(a[3]), "r"(b[0]), "r"(b[1]));
}
__device__ __forceinline__ uint32_t pack_half(float a, float b) {
    __half2 h = __floats2half2_rn(a, b);
    return *(uint32_t*)&h;
}

// ======================= conversion kernels ================================
__global__ __launch_bounds__(256)
void split_kernel(const float* __restrict__ in, __half* __restrict__ hi,
                  __half* __restrict__ lo, int n4)
{
    int i = blockIdx.x * blockDim.x + threadIdx.x;
    if (i >= n4) return;
    float4 v = ((const float4*)in)[i];
    __half h0 = __float2half_rn(v.x), h1 = __float2half_rn(v.y);
    __half h2 = __float2half_rn(v.z), h3 = __float2half_rn(v.w);
    __half l0 = __float2half_rn(v.x - __half2float(h0));
    __half l1 = __float2half_rn(v.y - __half2float(h1));
    __half l2 = __float2half_rn(v.z - __half2float(h2));
    __half l3 = __float2half_rn(v.w - __half2float(h3));
    ushort4 hv = make_ushort4(*(unsigned short*)&h0, *(unsigned short*)&h1,
                              *(unsigned short*)&h2, *(unsigned short*)&h3);
    ushort4 lv = make_ushort4(*(unsigned short*)&l0, *(unsigned short*)&l1,
                              *(unsigned short*)&l2, *(unsigned short*)&l3);
    ((ushort4*)hi)[i] = hv;
    ((ushort4*)lo)[i] = lv;
}

// W[K][N] fp32 -> T[N][K] single fp16 (transpose)
__global__ __launch_bounds__(256)
void transpose_half_kernel(const float* __restrict__ W, __half* __restrict__ T,
                           int K, int N)
{
    __shared__ float t[32][33];
    int n0 = blockIdx.x * 32, k0 = blockIdx.y * 32;
    int tx = threadIdx.x & 31, ty = threadIdx.x >> 5;
#pragma unroll
    for (int i = 0; i < 4; i++)
        t[ty + i * 8][tx] = W[(size_t)(k0 + ty + i * 8) * N + n0 + tx];
    __syncthreads();
#pragma unroll
    for (int i = 0; i < 4; i++)
        T[(size_t)(n0 + ty + i * 8) * K + k0 + tx] = __float2half_rn(t[tx][ty + i * 8]);
}

// ======================= mma.sync GEMM (fp16 2-product) ====================
// C = (Ahi+Alo)[M,K] @ B[N,K]^T, fp32 acc. BM=BN=128, BK=32, 3-stage
// cp.async pipeline (wait_group 1), 256 thr, warps 4x2, warp tile 32x64.
// MODE 0: fp32 C out (O projection).  MODE 1: fused QKV, per-CTA dispatch.
#define GSTRIDE  40
#define GS_MAT   (128 * GSTRIDE * 2)        // 10240 B
#define GS_STAGE (3 * GS_MAT)               // 30720 B: Ahi|Alo|B
#define GSTAGES  3
#define GEMM_SMEM_BYTES (GSTAGES * GS_STAGE)  // 92160

template<int MODE>
__global__ __launch_bounds__(256, 2)
void gemm_mma(const __half* __restrict__ Ahi, const __half* __restrict__ Alo,
              const __half* __restrict__ B,
              float* __restrict__ C,
              const float* __restrict__ fcos, const float* __restrict__ fsin)
{
    extern __shared__ char smem[];
    const uint32_t sbase = smem_u32(smem);
    const int tid  = threadIdx.x;
    const int lane = tid & 31;
    const int wid  = tid >> 5;
    const int wm   = wid & 3;
    const int wn   = wid >> 2;
    const int rowBase = blockIdx.y * 128;
    const int colBase = blockIdx.x * 128;

    auto prefetch = [&](int slot, int k0) {
        uint32_t st = sbase + (uint32_t)slot * GS_STAGE;
#pragma unroll
        for (int c = 0; c < 2; c++) {
            int ch  = tid + c * 256;          // 0..511
            int row = ch >> 2;                // 0..127
            int kc  = (ch & 3) * 8;           // 0,8,16,24
            uint32_t sm = (uint32_t)(row * GSTRIDE + kc) * 2;
            size_t ga = (size_t)(rowBase + row) * KTOT + k0 + kc;
            size_t gb = (size_t)(colBase + row) * KTOT + k0 + kc;
            CP_ASYNC16(st + 0 * GS_MAT + sm, Ahi + ga);
            CP_ASYNC16(st + 1 * GS_MAT + sm, Alo + ga);
            CP_ASYNC16(st + 2 * GS_MAT + sm, B   + gb);
        }
        CP_COMMIT();
    };

    float acc[2][8][4];
#pragma unroll
    for (int mi = 0; mi < 2; mi++)
#pragma unroll
        for (int ni = 0; ni < 8; ni++)
#pragma unroll
            for (int r = 0; r < 4; r++) acc[mi][ni][r] = 0.0f;

    const int am  = (lane & 7) + ((lane >> 3) & 1) * 8;
    const int ak  = (lane >> 4) * 8;
    const int bn4 = (lane & 7) + ((lane >> 4) & 1) * 8;
    const int bk4 = ((lane >> 3) & 1) * 8;

    prefetch(0, 0);
    prefetch(1, 32);

    int slot = 0;
    for (int i = 0; i < NK; i++) {
        CP_WAIT1();
        __syncthreads();
        if (i + 2 < NK) prefetch((i + 2) % 3, (i + 2) * 32);
        else            CP_COMMIT();        // keep outstanding-group invariant

        const uint32_t st   = sbase + (uint32_t)slot * GS_STAGE;
        const uint32_t aHiB = st, aLoB = st + GS_MAT, bB = st + 2 * GS_MAT;
        slot = (slot + 1 == 3) ? 0 : slot + 1;

#pragma unroll
        for (int ks = 0; ks < 32; ks += 16) {
            uint32_t aHi[2][4], aLo[2][4];
#pragma unroll
            for (int mi = 0; mi < 2; mi++) {
                uint32_t off = (uint32_t)((wm * 32 + mi * 16 + am) * GSTRIDE + ks + ak) * 2;
                ldsm_x4(aHi[mi], aHiB + off);
                ldsm_x4(aLo[mi], aLoB + off);
            }
#pragma unroll
            for (int ni2 = 0; ni2 < 4; ni2++) {
                uint32_t boff = (uint32_t)((wn * 64 + ni2 * 16 + bn4) * GSTRIDE + ks + bk4) * 2;
                uint32_t bh[4];
                ldsm_x4(bh, bB + boff);
#pragma unroll
                for (int mi = 0; mi < 2; mi++) {
                    mma16816h(acc[mi][2 * ni2],     aHi[mi], bh);
                    mma16816h(acc[mi][2 * ni2 + 1], aHi[mi], bh + 2);
                    mma16816h(acc[mi][2 * ni2],     aLo[mi], bh);
                    mma16816h(acc[mi][2 * ni2 + 1], aLo[mi], bh + 2);
                }
            }
        }
        // no bottom barrier: prefetch targets a stage whose readers all
        // passed a later top barrier.
    }

    // ---- epilogue ----
    const int qrow = lane >> 2;
    const int qcol = (lane & 3) * 2;

    int region = 0, Nout = DIM, colOff = colBase;    // MODE 1 dispatch
    if (MODE == 1) {
        if (colBase < DIM)              { region = 0; Nout = DIM;   colOff = colBase; }
        else if (colBase < DIM + KVDIM) { region = 1; Nout = KVDIM; colOff = colBase - DIM; }
        else                            { region = 2; Nout = KVDIM; colOff = colBase - DIM - KVDIM; }
    }
    const float osc = 0.08838834764831844f;          // 1/sqrt(128), Q only

#pragma unroll
    for (int mi = 0; mi < 2; mi++) {
#pragma unroll
        for (int half = 0; half < 2; half++) {
            int r = rowBase + wm * 32 + mi * 16 + qrow + half * 8;
#pragma unroll
            for (int ni = 0; ni < 8; ni++) {
                int n_g = colOff + wn * 64 + ni * 8 + qcol;
                float c0 = acc[mi][ni][half * 2];
                float c1 = acc[mi][ni][half * 2 + 1];
                if (MODE == 0) {
                    *(float2*)&C[(size_t)r * DIM + n_g] = make_float2(c0, c1);
                } else {
                    float ox = c0, oy = c1;
                    if (region < 2) {                 // rope for Q and K
                        int d = (n_g & (HD - 1)) >> 1;
                        float fc = fcos[r * (HD / 2) + d];
                        float fs = fsin[r * (HD / 2) + d];
                        ox = c0 * fc - c1 * fs;
                        oy = c0 * fs + c1 * fc;
                    }
                    size_t o = (size_t)r * Nout + n_g;
                    if (region == 0) {                // Q: scale + split
                        ox *= osc; oy *= osc;
                        __half h0 = __float2half_rn(ox);
                        __half h1 = __float2half_rn(oy);
                        *(uint32_t*)&g_qhi[o] = pack_half(__half2float(h0), __half2float(h1));
                        *(uint32_t*)&g_qlo[o] = pack_half(ox - __half2float(h0),
                                                          oy - __half2float(h1));
                    } else if (region == 1) {         // K: single fp16
                        *(uint32_t*)&g_k[o] = pack_half(ox, oy);
                    } else {                          // V: single fp16
                        *(uint32_t*)&g_v[o] = pack_half(ox, oy);
                    }
                }
            }
        }
    }
}

// ======================= flash attention (fp16 2-product) ==================
#define FPAD 136
#define FQ_BYTES   (128 * FPAD * 2)        // 34816
#define FT_BYTES   (64 * FPAD * 2)         // 17408
#define FKV_BYTES  (2 * FT_BYTES)          // 34816: K | V
#define FLASH_SMEM (2 * FQ_BYTES + 2 * FKV_BYTES)   // 139264

__global__ __launch_bounds__(256, 1)
void flash_mma(const __half* __restrict__ qhi, const __half* __restrict__ qlo,
               const __half* __restrict__ k,  const __half* __restrict__ v,
               __half* __restrict__ atthi, __half* __restrict__ attlo)
{
    extern __shared__ char smem[];
    const uint32_t sbase = smem_u32(smem);
    const int tid  = threadIdx.x;
    const int lane = tid & 31;
    const int w    = tid >> 5;
    const int qt   = gridDim.x - 1 - blockIdx.x;
    const int head = blockIdx.y;
    const int kvh  = head >> 2;
    const int qbase = qt * 128;
    const int ktmax = 2 * qt + 1;

    const uint32_t QHI = sbase;
    const uint32_t QLO = sbase + FQ_BYTES;
    const uint32_t KVB = sbase + 2 * FQ_BYTES;

#pragma unroll
    for (int t = 0; t < 16; t++) {
        int c = tid + t * 256;            // 0..4095
        int arr = c >> 11;
        int rem = c & 2047;
        int row = rem >> 4;
        int ch  = rem & 15;
        const __half* src = arr ? qlo : qhi;
        uint32_t dst = (arr ? QLO : QHI) + (uint32_t)(row * FPAD + ch * 8) * 2;
        CP_ASYNC16(dst, src + (size_t)(qbase + row) * DIM + head * HD + ch * 8);
    }
    auto load_kv = [&](int buf, int kt) {
        const int kbase = kt * 64;
        uint32_t base = KVB + (uint32_t)buf * FKV_BYTES;
#pragma unroll
        for (int t = 0; t < 8; t++) {
            int c = tid + t * 256;        // 0..2047
            int arr = c >> 10;            // 0=K, 1=V
            int rem = c & 1023;
            int row = rem >> 4;
            int ch  = rem & 15;
            const __half* src = arr ? v : k;
            uint32_t dst = base + (uint32_t)arr * FT_BYTES + (uint32_t)(row * FPAD + ch * 8) * 2;
            CP_ASYNC16(dst, src + (size_t)(kbase + row) * KVDIM + kvh * HD + ch * 8);
        }
        CP_COMMIT();
    };
    load_kv(0, 0);   // one commit covering Q + tile 0

    const int am  = (lane & 7) + ((lane >> 3) & 1) * 8;
    const int ak  = (lane >> 4) * 8;
    const int kn4 = (lane & 7) + ((lane >> 4) & 1) * 8;
    const int kk4 = ((lane >> 3) & 1) * 8;
    const int vrow = ((lane >> 3) & 1) * 8 + (lane & 7);
    const int vcol = ((lane >> 4) & 1) * 8;
    const int qrow = lane >> 2;
    const int qcol = (lane & 3) * 2;

    float O[16][4];
#pragma unroll
    for (int ni = 0; ni < 16; ni++)
#pragma unroll
        for (int r = 0; r < 4; r++) O[ni][r] = 0.0f;
    float m0 = -1e30f, m1 = -1e30f, l0 = 0.0f, l1 = 0.0f;

    for (int kt = 0; kt <= ktmax; kt++) {
        CP_WAIT0();
        __syncthreads();
        if (kt + 1 <= ktmax) load_kv((kt + 1) & 1, kt + 1);

        const uint32_t base = KVB + (uint32_t)(kt & 1) * FKV_BYTES;
        const uint32_t KB = base, VB = base + FT_BYTES;

        // ---- S = (Qhi+Qlo) K^T ----
        float S[8][4];
#pragma unroll
        for (int j = 0; j < 8; j++)
#pragma unroll
            for (int r = 0; r < 4; r++) S[j][r] = 0.0f;

#pragma unroll
        for (int ks = 0; ks < 8; ks++) {
            uint32_t qh[4], ql[4];
            uint32_t qoff = (uint32_t)((w * 16 + am) * FPAD + ks * 16 + ak) * 2;
            ldsm_x4(qh, QHI + qoff);
            ldsm_x4(ql, QLO + qoff);
#pragma unroll
            for (int jp = 0; jp < 4; jp++) {
                uint32_t koff = (uint32_t)((jp * 16 + kn4) * FPAD + ks * 16 + kk4) * 2;
                uint32_t kh[4];
                ldsm_x4(kh, KB + koff);
                mma16816h(S[2 * jp],     qh, kh);
                mma16816h(S[2 * jp + 1], qh, kh + 2);
                mma16816h(S[2 * jp],     ql, kh);
                mma16816h(S[2 * jp + 1], ql, kh + 2);
            }
        }

        if (kt >= 2 * qt) {
            const int kbase = kt * 64;
            int gq0 = qbase + w * 16 + qrow;
            int gq1 = gq0 + 8;
#pragma unroll
            for (int j = 0; j < 8; j++) {
                int gk = kbase + j * 8 + qcol;
                if (gk     > gq0) S[j][0] = -1e30f;
                if (gk + 1 > gq0) S[j][1] = -1e30f;
                if (gk     > gq1) S[j][2] = -1e30f;
                if (gk + 1 > gq1) S[j][3] = -1e30f;
            }
        }

        float mx0 = -1e30f, mx1 = -1e30f;
#pragma unroll
        for (int j = 0; j < 8; j++) {
            mx0 = fmaxf(mx0, fmaxf(S[j][0], S[j][1]));
            mx1 = fmaxf(mx1, fmaxf(S[j][2], S[j][3]));
        }
        mx0 = fmaxf(mx0, __shfl_xor_sync(0xffffffffu, mx0, 1));
        mx0 = fmaxf(mx0, __shfl_xor_sync(0xffffffffu, mx0, 2));
        mx1 = fmaxf(mx1, __shfl_xor_sync(0xffffffffu, mx1, 1));
        mx1 = fmaxf(mx1, __shfl_xor_sync(0xffffffffu, mx1, 2));

        float m0n = fmaxf(m0, mx0), m1n = fmaxf(m1, mx1);
        float a0 = __expf(m0 - m0n), a1 = __expf(m1 - m1n);
        float s0 = 0.0f, s1 = 0.0f;
#pragma unroll
        for (int j = 0; j < 8; j++) {
            S[j][0] = __expf(S[j][0] - m0n);
            S[j][1] = __expf(S[j][1] - m0n);
            S[j][2] = __expf(S[j][2] - m1n);
            S[j][3] = __expf(S[j][3] - m1n);
            s0 += S[j][0] + S[j][1];
            s1 += S[j][2] + S[j][3];
        }
        s0 += __shfl_xor_sync(0xffffffffu, s0, 1);
        s0 += __shfl_xor_sync(0xffffffffu, s0, 2);
        s1 += __shfl_xor_sync(0xffffffffu, s1, 1);
        s1 += __shfl_xor_sync(0xffffffffu, s1, 2);
        l0 = l0 * a0 + s0;  m0 = m0n;
        l1 = l1 * a1 + s1;  m1 = m1n;
#pragma unroll
        for (int ni = 0; ni < 16; ni++) {
            O[ni][0] *= a0; O[ni][1] *= a0;
            O[ni][2] *= a1; O[ni][3] *= a1;
        }

        // ---- O += (Phi+Plo) V ----
#pragma unroll
        for (int kt2 = 0; kt2 < 4; kt2++) {
            uint32_t ph[4], pl[4];
#pragma unroll
            for (int half = 0; half < 2; half++) {
                float p0 = S[2 * kt2 + half][0], p1 = S[2 * kt2 + half][1];
                float p2 = S[2 * kt2 + half][2], p3 = S[2 * kt2 + half][3];
                __half q0 = __float2half_rn(p0), q1 = __float2half_rn(p1);
                __half q2 = __float2half_rn(p2), q3 = __float2half_rn(p3);
                float h0 = __half2float(q0), h1 = __half2float(q1);
                float h2 = __half2float(q2), h3 = __half2float(q3);
                ph[half * 2 + 0] = pack_half(h0, h1);
                ph[half * 2 + 1] = pack_half(h2, h3);
                pl[half * 2 + 0] = pack_half(p0 - h0, p1 - h1);
                pl[half * 2 + 1] = pack_half(p2 - h2, p3 - h3);
            }
#pragma unroll
            for (int nip = 0; nip < 8; nip++) {
                uint32_t voff = (uint32_t)((kt2 * 16 + vrow) * FPAD + nip * 16 + vcol) * 2;
                uint32_t vh[4];
                ldsm_x4t(vh, VB + voff);
                mma16816h(O[2 * nip],     ph, vh);
                mma16816h(O[2 * nip + 1], ph, vh + 2);
                mma16816h(O[2 * nip],     pl, vh);
                mma16816h(O[2 * nip + 1], pl, vh + 2);
            }
        }
    }

    float inv0 = 1.0f / l0, inv1 = 1.0f / l1;
    int gq0 = qbase + w * 16 + qrow;
    int gq1 = gq0 + 8;
#pragma unroll
    for (int ni = 0; ni < 16; ni++) {
        int col = head * HD + ni * 8 + qcol;
        float o0 = O[ni][0] * inv0, o1 = O[ni][1] * inv0;
        float o2 = O[ni][2] * inv1, o3 = O[ni][3] * inv1;
        __half e0 = __float2half_rn(o0), e1 = __float2half_rn(o1);
        __half e2 = __float2half_rn(o2), e3 = __float2half_rn(o3);
        float h0 = __half2float(e0), h1 = __half2float(e1);
        float h2 = __half2float(e2), h3 = __half2float(e3);
        size_t p0 = (size_t)gq0 * DIM + col;
        size_t p1 = (size_t)gq1 * DIM + col;
        *(uint32_t*)&atthi[p0] = pack_half(h0, h1);
        *(uint32_t*)&attlo[p0] = pack_half(o0 - h0, o1 - h1);
        *(uint32_t*)&atthi[p1] = pack_half(h2, h3);
        *(uint32_t*)&attlo[p1] = pack_half(o2 - h2, o3 - h3);
    }
}

// ======================= launch ============================================
extern "C" void kernel_launch(void* const* d_in, const int* in_sizes, int n_in,
                              void* d_out, int out_size)
{
    const float* x    = (const float*)d_in[0];
    const float* wq   = (const float*)d_in[1];
    const float* wk   = (const float*)d_in[2];
    const float* wv   = (const float*)d_in[3];
    const float* wo   = (const float*)d_in[4];
    const float* fcos = (const float*)d_in[5];
    const float* fsin = (const float*)d_in[6];
    float* out = (float*)d_out;

    __half *xhi, *xlo, *wqkvt, *wot, *qhi, *qlo, *kk, *vv, *atthi, *attlo;
    cudaGetSymbolAddress((void**)&xhi,   g_xhi);
    cudaGetSymbolAddress((void**)&xlo,   g_xlo);
    cudaGetSymbolAddress((void**)&wqkvt, g_wqkvt);
    cudaGetSymbolAddress((void**)&wot,   g_wot);
    cudaGetSymbolAddress((void**)&qhi,   g_qhi);
    cudaGetSymbolAddress((void**)&qlo,   g_qlo);
    cudaGetSymbolAddress((void**)&kk,    g_k);
    cudaGetSymbolAddress((void**)&vv,    g_v);
    cudaGetSymbolAddress((void**)&atthi, g_atthi);
    cudaGetSymbolAddress((void**)&attlo, g_attlo);

    cudaFuncSetAttribute(gemm_mma<0>,
                         cudaFuncAttributeMaxDynamicSharedMemorySize, GEMM_SMEM_BYTES);
    cudaFuncSetAttribute(gemm_mma<1>,
                         cudaFuncAttributeMaxDynamicSharedMemorySize, GEMM_SMEM_BYTES);
    cudaFuncSetAttribute(flash_mma,
                         cudaFuncAttributeMaxDynamicSharedMemorySize, FLASH_SMEM);

    int n4x = S_LEN * DIM / 4;

    split_kernel<<<(n4x + 255) / 256, 256>>>(x, xhi, xlo, n4x);
    transpose_half_kernel<<<dim3(DIM / 32,   DIM / 32), 256>>>(wq, wqkvt, KTOT, DIM);
    transpose_half_kernel<<<dim3(KVDIM / 32, DIM / 32), 256>>>(
        wk, wqkvt + (size_t)DIM * KTOT, KTOT, KVDIM);
    transpose_half_kernel<<<dim3(KVDIM / 32, DIM / 32), 256>>>(
        wv, wqkvt + (size_t)(DIM + KVDIM) * KTOT, KTOT, KVDIM);
    transpose_half_kernel<<<dim3(DIM / 32,   DIM / 32), 256>>>(wo, wot, KTOT, DIM);

    gemm_mma<1><<<dim3(NQKV / 128, S_LEN / 128), 256, GEMM_SMEM_BYTES>>>(
        xhi, xlo, wqkvt, nullptr, fcos, fsin);

    flash_mma<<<dim3(S_LEN / 128, NH), 256, FLASH_SMEM>>>(
        qhi, qlo, kk, vv, atthi, attlo);

    gemm_mma<0><<<dim3(DIM / 128, S_LEN / 128), 256, GEMM_SMEM_BYTES>>>(
        atthi, attlo, wot, out, nullptr, nullptr);
}

// round 14
// speedup vs baseline: 1.6649x; 1.0162x over previous
#include <cuda_runtime.h>
#include <cuda_fp16.h>
#include <math.h>
#include <stdint.h>

#define DIM   4096
#define S_LEN 2048
#define HD    128
#define NH    32
#define NKV   8
#define KVDIM (NKV*HD)   // 1024
#define KTOT  4096
#define NK    (KTOT/32)  // 128
#define NQKV  (DIM + 2*KVDIM)   // 6144

// ======================= scratch globals ===================================
__device__ __half g_xhi [S_LEN * DIM];
__device__ __half g_xlo [S_LEN * DIM];
__device__ __half g_wqkvt[NQKV * KTOT];   // single fp16: wq^T | wk^T | wv^T
__device__ __half g_wot  [DIM * KTOT];
__device__ __half g_qhi [S_LEN * DIM];
__device__ __half g_qlo [S_LEN * DIM];
__device__ __half g_k   [S_LEN * KVDIM];
__device__ __half g_v   [S_LEN * KVDIM];
__device__ __half g_atthi[S_LEN * DIM];
__device__ __half g_attlo[S_LEN * DIM];

// ======================= asm helpers (sm_100-safe) =========================
__device__ __forceinline__ uint32_t smem_u32(const void* p) {
    uint32_t a;
    asm("{ .reg .u64 t; cvta.to.shared.u64 t, %1; cvt.u32.u64 %0, t; }"
        : "=r"(a) : "l"(p));
    return a;
}
#define CP_ASYNC16(dst, src) \
    asm volatile("cp.async.cg.shared.global [%0], [%1], 16;" :: "r"(dst), "l"(src))
#define CP_COMMIT()  asm volatile("cp.async.commit_group;" ::: "memory")
#define CP_WAIT0()   asm volatile("cp.async.wait_group 0;"  ::: "memory")
#define CP_WAIT1()   asm volatile("cp.async.wait_group 1;"  ::: "memory")

__device__ __forceinline__ void ldsm_x4(uint32_t* r, uint32_t addr) {
    asm volatile("ldmatrix.sync.aligned.m8n8.x4.shared.b16 {%0,%1,%2,%3}, [%4];"
                 : "=r"(r[0]), "=r"(r[1]), "=r"(r[2]), "=r"(r[3]) : "r"(addr));
}
__device__ __forceinline__ void ldsm_x4t(uint32_t* r, uint32_t addr) {
    asm volatile("ldmatrix.sync.aligned.m8n8.x4.trans.shared.b16 {%0,%1,%2,%3}, [%4];"
                 : "=r"(r[0]), "=r"(r[1]), "=r"(r[2]), "=r"(r[3]) : "r"(addr));
}
__device__ __forceinline__ void mma16816h(float* c, const uint32_t* a, const uint32_t* b) {
    asm volatile("mma.sync.aligned.m16n8k16.row.col.f32.f16.f16.f32 "
                 "{%0,%1,%2,%3}, {%4,%5,%6,%7}, {%8,%9}, {%0,%1,%2,%3};"
                 : "+f"(c[0]), "+f"(c[1]), "+f"(c[2]), "+f"(c[3])
                 : "r"(a[0]), "r"(a[1]), "r"(a[2]), "r"(a[3]), "r"(b[0]), "r"(b[1]));
}
__device__ __forceinline__ uint32_t pack_half(float a, float b) {
    __half2 h = __floats2half2_rn(a, b);
    return *(uint32_t*)&h;
}

// ======================= conversion kernels ================================
__global__ __launch_bounds__(256)
void split_kernel(const float* __restrict__ in, __half* __restrict__ hi,
                  __half* __restrict__ lo, int n4)
{
    int i = blockIdx.x * blockDim.x + threadIdx.x;
    if (i >= n4) return;
    float4 v = ((const float4*)in)[i];
    __half h0 = __float2half_rn(v.x), h1 = __float2half_rn(v.y);
    __half h2 = __float2half_rn(v.z), h3 = __float2half_rn(v.w);
    __half l0 = __float2half_rn(v.x - __half2float(h0));
    __half l1 = __float2half_rn(v.y - __half2float(h1));
    __half l2 = __float2half_rn(v.z - __half2float(h2));
    __half l3 = __float2half_rn(v.w - __half2float(h3));
    ushort4 hv = make_ushort4(*(unsigned short*)&h0, *(unsigned short*)&h1,
                              *(unsigned short*)&h2, *(unsigned short*)&h3);
    ushort4 lv = make_ushort4(*(unsigned short*)&l0, *(unsigned short*)&l1,
                              *(unsigned short*)&l2, *(unsigned short*)&l3);
    ((ushort4*)hi)[i] = hv;
    ((ushort4*)lo)[i] = lv;
}

// W[K][N] fp32 -> T[N][K] single fp16 (transpose)
__global__ __launch_bounds__(256)
void transpose_half_kernel(const float* __restrict__ W, __half* __restrict__ T,
                           int K, int N)
{
    __shared__ float t[32][33];
    int n0 = blockIdx.x * 32, k0 = blockIdx.y * 32;
    int tx = threadIdx.x & 31, ty = threadIdx.x >> 5;
#pragma unroll
    for (int i = 0; i < 4; i++)
        t[ty + i * 8][tx] = W[(size_t)(k0 + ty + i * 8) * N + n0 + tx];
    __syncthreads();
#pragma unroll
    for (int i = 0; i < 4; i++)
        T[(size_t)(n0 + ty + i * 8) * K + k0 + tx] = __float2half_rn(t[tx][ty + i * 8]);
}

// ======================= mma.sync GEMM (fp16 2-product) ====================
// C = (Ahi+Alo)[M,K] @ B[N,K]^T, fp32 acc. BM=BN=128, BK=32, 3-stage
// cp.async pipeline (wait_group 1), 256 thr, warps 4x2, warp tile 32x64.
// MODE 0: fp32 C out (O projection).  MODE 1: fused QKV, per-CTA dispatch.
#define GSTRIDE  40
#define GS_MAT   (128 * GSTRIDE * 2)        // 10240 B
#define GS_STAGE (3 * GS_MAT)               // 30720 B: Ahi|Alo|B
#define GSTAGES  3
#define GEMM_SMEM_BYTES (GSTAGES * GS_STAGE)  // 92160

template<int MODE>
__global__ __launch_bounds__(256, 2)
void gemm_mma(const __half* __restrict__ Ahi, const __half* __restrict__ Alo,
              const __half* __restrict__ B,
              float* __restrict__ C,
              const float* __restrict__ fcos, const float* __restrict__ fsin)
{
    extern __shared__ char smem[];
    const uint32_t sbase = smem_u32(smem);
    const int tid  = threadIdx.x;
    const int lane = tid & 31;
    const int wid  = tid >> 5;
    const int wm   = wid & 3;
    const int wn   = wid >> 2;
    const int rowBase = blockIdx.y * 128;
    const int colBase = blockIdx.x * 128;

    auto prefetch = [&](int slot, int k0) {
        uint32_t st = sbase + (uint32_t)slot * GS_STAGE;
#pragma unroll
        for (int c = 0; c < 2; c++) {
            int ch  = tid + c * 256;          // 0..511
            int row = ch >> 2;                // 0..127
            int kc  = (ch & 3) * 8;           // 0,8,16,24
            uint32_t sm = (uint32_t)(row * GSTRIDE + kc) * 2;
            size_t ga = (size_t)(rowBase + row) * KTOT + k0 + kc;
            size_t gb = (size_t)(colBase + row) * KTOT + k0 + kc;
            CP_ASYNC16(st + 0 * GS_MAT + sm, Ahi + ga);
            CP_ASYNC16(st + 1 * GS_MAT + sm, Alo + ga);
            CP_ASYNC16(st + 2 * GS_MAT + sm, B   + gb);
        }
        CP_COMMIT();
    };

    float acc[2][8][4];
#pragma unroll
    for (int mi = 0; mi < 2; mi++)
#pragma unroll
        for (int ni = 0; ni < 8; ni++)
#pragma unroll
            for (int r = 0; r < 4; r++) acc[mi][ni][r] = 0.0f;

    const int am  = (lane & 7) + ((lane >> 3) & 1) * 8;
    const int ak  = (lane >> 4) * 8;
    const int bn4 = (lane & 7) + ((lane >> 4) & 1) * 8;
    const int bk4 = ((lane >> 3) & 1) * 8;

    prefetch(0, 0);
    prefetch(1, 32);

    int slot = 0;
    for (int i = 0; i < NK; i++) {
        CP_WAIT1();
        __syncthreads();
        if (i + 2 < NK) prefetch((i + 2) % 3, (i + 2) * 32);
        else            CP_COMMIT();        // keep outstanding-group invariant

        const uint32_t st   = sbase + (uint32_t)slot * GS_STAGE;
        const uint32_t aHiB = st, aLoB = st + GS_MAT, bB = st + 2 * GS_MAT;
        slot = (slot + 1 == 3) ? 0 : slot + 1;

#pragma unroll
        for (int ks = 0; ks < 32; ks += 16) {
            uint32_t aHi[2][4], aLo[2][4];
#pragma unroll
            for (int mi = 0; mi < 2; mi++) {
                uint32_t off = (uint32_t)((wm * 32 + mi * 16 + am) * GSTRIDE + ks + ak) * 2;
                ldsm_x4(aHi[mi], aHiB + off);
                ldsm_x4(aLo[mi], aLoB + off);
            }
#pragma unroll
            for (int ni2 = 0; ni2 < 4; ni2++) {
                uint32_t boff = (uint32_t)((wn * 64 + ni2 * 16 + bn4) * GSTRIDE + ks + bk4) * 2;
                uint32_t bh[4];
                ldsm_x4(bh, bB + boff);
#pragma unroll
                for (int mi = 0; mi < 2; mi++) {
                    mma16816h(acc[mi][2 * ni2],     aHi[mi], bh);
                    mma16816h(acc[mi][2 * ni2 + 1], aHi[mi], bh + 2);
                    mma16816h(acc[mi][2 * ni2],     aLo[mi], bh);
                    mma16816h(acc[mi][2 * ni2 + 1], aLo[mi], bh + 2);
                }
            }
        }
        // no bottom barrier: prefetch targets a stage whose readers all
        // passed a later top barrier.
    }

    // ---- epilogue ----
    const int qrow = lane >> 2;
    const int qcol = (lane & 3) * 2;

    int region = 0, Nout = DIM, colOff = colBase;    // MODE 1 dispatch
    if (MODE == 1) {
        if (colBase < DIM)              { region = 0; Nout = DIM;   colOff = colBase; }
        else if (colBase < DIM + KVDIM) { region = 1; Nout = KVDIM; colOff = colBase - DIM; }
        else                            { region = 2; Nout = KVDIM; colOff = colBase - DIM - KVDIM; }
    }
    const float osc = 0.08838834764831844f;          // 1/sqrt(128), Q only

#pragma unroll
    for (int mi = 0; mi < 2; mi++) {
#pragma unroll
        for (int half = 0; half < 2; half++) {
            int r = rowBase + wm * 32 + mi * 16 + qrow + half * 8;
#pragma unroll
            for (int ni = 0; ni < 8; ni++) {
                int n_g = colOff + wn * 64 + ni * 8 + qcol;
                float c0 = acc[mi][ni][half * 2];
                float c1 = acc[mi][ni][half * 2 + 1];
                if (MODE == 0) {
                    *(float2*)&C[(size_t)r * DIM + n_g] = make_float2(c0, c1);
                } else {
                    float ox = c0, oy = c1;
                    if (region < 2) {                 // rope for Q and K
                        int d = (n_g & (HD - 1)) >> 1;
                        float fc = fcos[r * (HD / 2) + d];
                        float fs = fsin[r * (HD / 2) + d];
                        ox = c0 * fc - c1 * fs;
                        oy = c0 * fs + c1 * fc;
                    }
                    size_t o = (size_t)r * Nout + n_g;
                    if (region == 0) {                // Q: scale + split
                        ox *= osc; oy *= osc;
                        __half h0 = __float2half_rn(ox);
                        __half h1 = __float2half_rn(oy);
                        *(uint32_t*)&g_qhi[o] = pack_half(__half2float(h0), __half2float(h1));
                        *(uint32_t*)&g_qlo[o] = pack_half(ox - __half2float(h0),
                                                          oy - __half2float(h1));
                    } else if (region == 1) {         // K: single fp16
                        *(uint32_t*)&g_k[o] = pack_half(ox, oy);
                    } else {                          // V: single fp16
                        *(uint32_t*)&g_v[o] = pack_half(ox, oy);
                    }
                }
            }
        }
    }
}

// ======================= flash attention (fp16 2-product) ==================
// BM=64 q rows (4 warps x m16), BN=64 keys/tile, 128 threads, 2 CTAs/SM.
#define FPAD 136
#define FQ_BYTES   (64 * FPAD * 2)         // 17408 (per Q split-matrix)
#define FT_BYTES   (64 * FPAD * 2)         // 17408
#define FKV_BYTES  (2 * FT_BYTES)          // 34816: K | V
#define FLASH_SMEM (2 * FQ_BYTES + 2 * FKV_BYTES)   // 104448

__global__ __launch_bounds__(128, 2)
void flash_mma(const __half* __restrict__ qhi, const __half* __restrict__ qlo,
               const __half* __restrict__ k,  const __half* __restrict__ v,
               __half* __restrict__ atthi, __half* __restrict__ attlo)
{
    extern __shared__ char smem[];
    const uint32_t sbase = smem_u32(smem);
    const int tid  = threadIdx.x;
    const int lane = tid & 31;
    const int w    = tid >> 5;            // 4 warps: rows w*16..w*16+15
    const int qt   = gridDim.x - 1 - blockIdx.x;   // big tiles first
    const int head = blockIdx.y;
    const int kvh  = head >> 2;
    const int qbase = qt * 64;
    const int ktmax = qt;

    const uint32_t QHI = sbase;
    const uint32_t QLO = sbase + FQ_BYTES;
    const uint32_t KVB = sbase + 2 * FQ_BYTES;

#pragma unroll
    for (int t = 0; t < 16; t++) {
        int c = tid + t * 128;            // 0..2047
        int arr = c >> 10;                // 0=hi, 1=lo
        int rem = c & 1023;
        int row = rem >> 4;               // 0..63
        int ch  = rem & 15;
        const __half* src = arr ? qlo : qhi;
        uint32_t dst = (arr ? QLO : QHI) + (uint32_t)(row * FPAD + ch * 8) * 2;
        CP_ASYNC16(dst, src + (size_t)(qbase + row) * DIM + head * HD + ch * 8);
    }
    auto load_kv = [&](int buf, int kt) {
        const int kbase = kt * 64;
        uint32_t base = KVB + (uint32_t)buf * FKV_BYTES;
#pragma unroll
        for (int t = 0; t < 16; t++) {
            int c = tid + t * 128;        // 0..2047
            int arr = c >> 10;            // 0=K, 1=V
            int rem = c & 1023;
            int row = rem >> 4;
            int ch  = rem & 15;
            const __half* src = arr ? v : k;
            uint32_t dst = base + (uint32_t)arr * FT_BYTES + (uint32_t)(row * FPAD + ch * 8) * 2;
            CP_ASYNC16(dst, src + (size_t)(kbase + row) * KVDIM + kvh * HD + ch * 8);
        }
        CP_COMMIT();
    };
    load_kv(0, 0);   // one commit covering Q + tile 0

    const int am  = (lane & 7) + ((lane >> 3) & 1) * 8;
    const int ak  = (lane >> 4) * 8;
    const int kn4 = (lane & 7) + ((lane >> 4) & 1) * 8;
    const int kk4 = ((lane >> 3) & 1) * 8;
    const int vrow = ((lane >> 3) & 1) * 8 + (lane & 7);
    const int vcol = ((lane >> 4) & 1) * 8;
    const int qrow = lane >> 2;
    const int qcol = (lane & 3) * 2;

    float O[16][4];
#pragma unroll
    for (int ni = 0; ni < 16; ni++)
#pragma unroll
        for (int r = 0; r < 4; r++) O[ni][r] = 0.0f;
    float m0 = -1e30f, m1 = -1e30f, l0 = 0.0f, l1 = 0.0f;

    for (int kt = 0; kt <= ktmax; kt++) {
        CP_WAIT0();
        __syncthreads();
        if (kt + 1 <= ktmax) load_kv((kt + 1) & 1, kt + 1);

        const uint32_t base = KVB + (uint32_t)(kt & 1) * FKV_BYTES;
        const uint32_t KB = base, VB = base + FT_BYTES;

        // ---- S = (Qhi+Qlo) K^T ----
        float S[8][4];
#pragma unroll
        for (int j = 0; j < 8; j++)
#pragma unroll
            for (int r = 0; r < 4; r++) S[j][r] = 0.0f;

#pragma unroll
        for (int ks = 0; ks < 8; ks++) {
            uint32_t qh[4], ql[4];
            uint32_t qoff = (uint32_t)((w * 16 + am) * FPAD + ks * 16 + ak) * 2;
            ldsm_x4(qh, QHI + qoff);
            ldsm_x4(ql, QLO + qoff);
#pragma unroll
            for (int jp = 0; jp < 4; jp++) {
                uint32_t koff = (uint32_t)((jp * 16 + kn4) * FPAD + ks * 16 + kk4) * 2;
                uint32_t kh[4];
                ldsm_x4(kh, KB + koff);
                mma16816h(S[2 * jp],     qh, kh);
                mma16816h(S[2 * jp + 1], qh, kh + 2);
                mma16816h(S[2 * jp],     ql, kh);
                mma16816h(S[2 * jp + 1], ql, kh + 2);
            }
        }

        if (kt == qt) {                    // diagonal tile only
            const int kbase = kt * 64;
            int gq0 = qbase + w * 16 + qrow;
            int gq1 = gq0 + 8;
#pragma unroll
            for (int j = 0; j < 8; j++) {
                int gk = kbase + j * 8 + qcol;
                if (gk     > gq0) S[j][0] = -1e30f;
                if (gk + 1 > gq0) S[j][1] = -1e30f;
                if (gk     > gq1) S[j][2] = -1e30f;
                if (gk + 1 > gq1) S[j][3] = -1e30f;
            }
        }

        float mx0 = -1e30f, mx1 = -1e30f;
#pragma unroll
        for (int j = 0; j < 8; j++) {
            mx0 = fmaxf(mx0, fmaxf(S[j][0], S[j][1]));
            mx1 = fmaxf(mx1, fmaxf(S[j][2], S[j][3]));
        }
        mx0 = fmaxf(mx0, __shfl_xor_sync(0xffffffffu, mx0, 1));
        mx0 = fmaxf(mx0, __shfl_xor_sync(0xffffffffu, mx0, 2));
        mx1 = fmaxf(mx1, __shfl_xor_sync(0xffffffffu, mx1, 1));
        mx1 = fmaxf(mx1, __shfl_xor_sync(0xffffffffu, mx1, 2));

        float m0n = fmaxf(m0, mx0), m1n = fmaxf(m1, mx1);
        float a0 = __expf(m0 - m0n), a1 = __expf(m1 - m1n);
        float s0 = 0.0f, s1 = 0.0f;
#pragma unroll
        for (int j = 0; j < 8; j++) {
            S[j][0] = __expf(S[j][0] - m0n);
            S[j][1] = __expf(S[j][1] - m0n);
            S[j][2] = __expf(S[j][2] - m1n);
            S[j][3] = __expf(S[j][3] - m1n);
            s0 += S[j][0] + S[j][1];
            s1 += S[j][2] + S[j][3];
        }
        s0 += __shfl_xor_sync(0xffffffffu, s0, 1);
        s0 += __shfl_xor_sync(0xffffffffu, s0, 2);
        s1 += __shfl_xor_sync(0xffffffffu, s1, 1);
        s1 += __shfl_xor_sync(0xffffffffu, s1, 2);
        l0 = l0 * a0 + s0;  m0 = m0n;
        l1 = l1 * a1 + s1;  m1 = m1n;
#pragma unroll
        for (int ni = 0; ni < 16; ni++) {
            O[ni][0] *= a0; O[ni][1] *= a0;
            O[ni][2] *= a1; O[ni][3] *= a1;
        }

        // ---- O += (Phi+Plo) V ----
#pragma unroll
        for (int kt2 = 0; kt2 < 4; kt2++) {
            uint32_t ph[4], pl[4];
#pragma unroll
            for (int half = 0; half < 2; half++) {
                float p0 = S[2 * kt2 + half][0], p1 = S[2 * kt2 + half][1];
                float p2 = S[2 * kt2 + half][2], p3 = S[2 * kt2 + half][3];
                __half q0 = __float2half_rn(p0), q1 = __float2half_rn(p1);
                __half q2 = __float2half_rn(p2), q3 = __float2half_rn(p3);
                float h0 = __half2float(q0), h1 = __half2float(q1);
                float h2 = __half2float(q2), h3 = __half2float(q3);
                ph[half * 2 + 0] = pack_half(h0, h1);
                ph[half * 2 + 1] = pack_half(h2, h3);
                pl[half * 2 + 0] = pack_half(p0 - h0, p1 - h1);
                pl[half * 2 + 1] = pack_half(p2 - h2, p3 - h3);
            }
#pragma unroll
            for (int nip = 0; nip < 8; nip++) {
                uint32_t voff = (uint32_t)((kt2 * 16 + vrow) * FPAD + nip * 16 + vcol) * 2;
                uint32_t vh[4];
                ldsm_x4t(vh, VB + voff);
                mma16816h(O[2 * nip],     ph, vh);
                mma16816h(O[2 * nip + 1], ph, vh + 2);
                mma16816h(O[2 * nip],     pl, vh);
                mma16816h(O[2 * nip + 1], pl, vh + 2);
            }
        }
    }

    float inv0 = 1.0f / l0, inv1 = 1.0f / l1;
    int gq0 = qbase + w * 16 + qrow;
    int gq1 = gq0 + 8;
#pragma unroll
    for (int ni = 0; ni < 16; ni++) {
        int col = head * HD + ni * 8 + qcol;
        float o0 = O[ni][0] * inv0, o1 = O[ni][1] * inv0;
        float o2 = O[ni][2] * inv1, o3 = O[ni][3] * inv1;
        __half e0 = __float2half_rn(o0), e1 = __float2half_rn(o1);
        __half e2 = __float2half_rn(o2), e3 = __float2half_rn(o3);
        float h0 = __half2float(e0), h1 = __half2float(e1);
        float h2 = __half2float(e2), h3 = __half2float(e3);
        size_t p0 = (size_t)gq0 * DIM + col;
        size_t p1 = (size_t)gq1 * DIM + col;
        *(uint32_t*)&atthi[p0] = pack_half(h0, h1);
        *(uint32_t*)&attlo[p0] = pack_half(o0 - h0, o1 - h1);
        *(uint32_t*)&atthi[p1] = pack_half(h2, h3);
        *(uint32_t*)&attlo[p1] = pack_half(o2 - h2, o3 - h3);
    }
}

// ======================= launch ============================================
extern "C" void kernel_launch(void* const* d_in, const int* in_sizes, int n_in,
                              void* d_out, int out_size)
{
    const float* x    = (const float*)d_in[0];
    const float* wq   = (const float*)d_in[1];
    const float* wk   = (const float*)d_in[2];
    const float* wv   = (const float*)d_in[3];
    const float* wo   = (const float*)d_in[4];
    const float* fcos = (const float*)d_in[5];
    const float* fsin = (const float*)d_in[6];
    float* out = (float*)d_out;

    __half *xhi, *xlo, *wqkvt, *wot, *qhi, *qlo, *kk, *vv, *atthi, *attlo;
    cudaGetSymbolAddress((void**)&xhi,   g_xhi);
    cudaGetSymbolAddress((void**)&xlo,   g_xlo);
    cudaGetSymbolAddress((void**)&wqkvt, g_wqkvt);
    cudaGetSymbolAddress((void**)&wot,   g_wot);
    cudaGetSymbolAddress((void**)&qhi,   g_qhi);
    cudaGetSymbolAddress((void**)&qlo,   g_qlo);
    cudaGetSymbolAddress((void**)&kk,    g_k);
    cudaGetSymbolAddress((void**)&vv,    g_v);
    cudaGetSymbolAddress((void**)&atthi, g_atthi);
    cudaGetSymbolAddress((void**)&attlo, g_attlo);

    cudaFuncSetAttribute(gemm_mma<0>,
                         cudaFuncAttributeMaxDynamicSharedMemorySize, GEMM_SMEM_BYTES);
    cudaFuncSetAttribute(gemm_mma<1>,
                         cudaFuncAttributeMaxDynamicSharedMemorySize, GEMM_SMEM_BYTES);
    cudaFuncSetAttribute(flash_mma,
                         cudaFuncAttributeMaxDynamicSharedMemorySize, FLASH_SMEM);

    int n4x = S_LEN * DIM / 4;

    split_kernel<<<(n4x + 255) / 256, 256>>>(x, xhi, xlo, n4x);
    transpose_half_kernel<<<dim3(DIM / 32,   DIM / 32), 256>>>(wq, wqkvt, KTOT, DIM);
    transpose_half_kernel<<<dim3(KVDIM / 32, DIM / 32), 256>>>(
        wk, wqkvt + (size_t)DIM * KTOT, KTOT, KVDIM);
    transpose_half_kernel<<<dim3(KVDIM / 32, DIM / 32), 256>>>(
        wv, wqkvt + (size_t)(DIM + KVDIM) * KTOT, KTOT, KVDIM);
    transpose_half_kernel<<<dim3(DIM / 32,   DIM / 32), 256>>>(wo, wot, KTOT, DIM);

    gemm_mma<1><<<dim3(NQKV / 128, S_LEN / 128), 256, GEMM_SMEM_BYTES>>>(
        xhi, xlo, wqkvt, nullptr, fcos, fsin);

    flash_mma<<<dim3(S_LEN / 64, NH), 128, FLASH_SMEM>>>(
        qhi, qlo, kk, vv, atthi, attlo);

    gemm_mma<0><<<dim3(DIM / 128, S_LEN / 128), 256, GEMM_SMEM_BYTES>>>(
        atthi, attlo, wot, out, nullptr, nullptr);
}